// round 16
// baseline (speedup 1.0000x reference)
#include <cuda_runtime.h>
#include <cuda_fp16.h>
#include <cstdint>

#define NN 50000
#define EE 800000
#define HIDF 128
#define NCLS 40
#define LNEPS 1e-5f
#define PADH 136   // halves per smem row (272B): ldmatrix conflict-free

typedef unsigned long long ull;

// ---------------- scratch (device globals; no allocation allowed) ----------------
__device__ __half2 g_h16[(size_t)NN * 64];    // post-GEMM features (layer0: unscaled)
__device__ __half2 g_act16[(size_t)NN * 64];  // post-LN activations (fp16)
__device__ float g_dinv[NN];
__device__ int   g_deg[NN];
__device__ int   g_start[NN];
__device__ int   g_rank[EE];
__device__ int   g_csrc[EE];
__device__ int   g_is64;
__device__ int   g_total;
__device__ ull   g_wpkh[12288];              // fp16 hi(W^T): [l][n][k]
__device__ ull   g_wpkl[12288];              // fp16 lo(W^T)
__device__ __half g_wouth[48 * 128];         // fp16 hi(Wout^T), padded n 40->48
__device__ __half g_woutl[48 * 128];         // fp16 lo(Wout^T)

__device__ __forceinline__ uint32_t smem_u32(const void* p) {
    uint32_t a;
    asm("{ .reg .u64 t; cvta.to.shared.u64 t, %1; cvt.u32.u64 %0, t; }" : "=r"(a) : "l"(p));
    return a;
}

// ---------------- HMMA helpers ----------------
__device__ __forceinline__ void mma16816(float* c, const uint32_t* a, const uint32_t* b) {
    asm volatile(
        "mma.sync.aligned.m16n8k16.row.col.f32.f16.f16.f32 "
        "{%0,%1,%2,%3}, {%4,%5,%6,%7}, {%8,%9}, {%0,%1,%2,%3};"
        : "+f"(c[0]), "+f"(c[1]), "+f"(c[2]), "+f"(c[3])
        : "r"(a[0]), "r"(a[1]), "r"(a[2]), "r"(a[3]), "r"(b[0]), "r"(b[1]));
}
__device__ __forceinline__ void ldmx4(uint32_t* r, const __half* p) {
    uint32_t a = smem_u32(p);
    asm volatile("ldmatrix.sync.aligned.m8n8.x4.shared.b16 {%0,%1,%2,%3}, [%4];"
                 : "=r"(r[0]), "=r"(r[1]), "=r"(r[2]), "=r"(r[3]) : "r"(a));
}

// ---------------- setup kernels (R11 configuration) ----------------
__global__ void detect_zero_kernel(const void* ei, int N) {
    int i = blockIdx.x * blockDim.x + threadIdx.x;
    for (int j = i; j < N; j += gridDim.x * blockDim.x) g_deg[j] = 0;
    if (blockIdx.x == 0 && threadIdx.x < 32) {
        const long long* p = (const long long*)ei;
        int lane = threadIdx.x;
        int bad = 0;
#pragma unroll
        for (int t = 0; t < 2; t++) {
            long long v = p[(lane + 32 * t) * 7];
            if (v < 0 || v >= NN) bad = 1;
        }
        unsigned m = __ballot_sync(0xffffffffu, bad);
        if (lane == 0) {
            g_is64 = (m == 0u);
            g_total = 0;
        }
    }
}

__global__ void convert_count(const void* __restrict__ ei, int E) {
    int e0 = (blockIdx.x * blockDim.x + threadIdx.x) * 2;
    if (e0 >= E) return;
    int d0, d1 = -1;
    if (g_is64) {
        const long long* p = (const long long*)ei;
        d0 = (int)p[E + e0];
        if (e0 + 1 < E) d1 = (int)p[E + e0 + 1];
    } else {
        const int* p = (const int*)ei;
        d0 = p[E + e0];
        if (e0 + 1 < E) d1 = p[E + e0 + 1];
    }
    g_rank[e0] = atomicAdd(&g_deg[d0], 1);
    if (d1 >= 0) g_rank[e0 + 1] = atomicAdd(&g_deg[d1], 1);
}

__global__ void alloc_kernel(int N) {
    __shared__ int warp_sums[32];
    __shared__ int block_base;
    int i = blockIdx.x * blockDim.x + threadIdx.x;
    int lane = threadIdx.x & 31;
    int wid = threadIdx.x >> 5;
    int dg = (i < N) ? g_deg[i] : 0;
    int pre = dg;
#pragma unroll
    for (int o = 1; o < 32; o <<= 1) {
        int v = __shfl_up_sync(0xffffffffu, pre, o);
        if (lane >= o) pre += v;
    }
    int wtot = __shfl_sync(0xffffffffu, pre, 31);
    int wexc = pre - dg;
    if (lane == 31) warp_sums[wid] = wtot;
    __syncthreads();
    if (wid == 0) {
        int v = (lane < (blockDim.x >> 5)) ? warp_sums[lane] : 0;
        int p = v;
#pragma unroll
        for (int o = 1; o < 32; o <<= 1) {
            int t = __shfl_up_sync(0xffffffffu, p, o);
            if (lane >= o) p += t;
        }
        int btot = __shfl_sync(0xffffffffu, p, 31);
        if (lane == 31) block_base = atomicAdd(&g_total, btot);
        p -= v;
        warp_sums[lane] = p;
    }
    __syncthreads();
    if (i < N) {
        g_start[i] = block_base + warp_sums[wid] + wexc;
        g_dinv[i] = rsqrtf((float)dg + 1.0f);
    }
}

__global__ void fill_kernel(const void* __restrict__ ei, int E) {
    int e0 = (blockIdx.x * blockDim.x + threadIdx.x) * 2;
    if (e0 >= E) return;
    int s0, d0, s1 = -1, d1 = -1;
    if (g_is64) {
        const long long* p = (const long long*)ei;
        s0 = (int)p[e0];
        d0 = (int)p[E + e0];
        if (e0 + 1 < E) { s1 = (int)p[e0 + 1]; d1 = (int)p[E + e0 + 1]; }
    } else {
        const int* p = (const int*)ei;
        s0 = p[e0];
        d0 = p[E + e0];
        if (e0 + 1 < E) { s1 = p[e0 + 1]; d1 = p[E + e0 + 1]; }
    }
    int st0 = g_start[d0];
    int rk0 = g_rank[e0];
    int st1 = 0, rk1 = 0;
    if (d1 >= 0) { st1 = g_start[d1]; rk1 = g_rank[e0 + 1]; }
    g_csrc[st0 + rk0] = s0;
    if (d1 >= 0) g_csrc[st1 + rk1] = s1;
}

__global__ void wprep_kernel(const float* __restrict__ cw) {
    int e = blockIdx.x * blockDim.x + threadIdx.x;
    if (e >= 3 * 16384) return;
    int l = e >> 14;
    int r = e & 16383;
    int k = r >> 7;
    int n = r & 127;
    float w = cw[e];
    __half h = __float2half_rn(w);
    __half lo = __float2half_rn(w - __half2float(h));
    size_t off = (size_t)l * 16384 + (size_t)n * 128 + k;
    ((__half*)g_wpkh)[off] = h;
    ((__half*)g_wpkl)[off] = lo;
}

__global__ void wprep_out_kernel(const float* __restrict__ wout) {
    int i = blockIdx.x * blockDim.x + threadIdx.x;
    if (i >= 48 * 128) return;
    int n = i >> 7;
    int k = i & 127;
    float w = (n < NCLS) ? wout[k * NCLS + n] : 0.f;
    __half h = __float2half_rn(w);
    __half lo = __float2half_rn(w - __half2float(h));
    g_wouth[i] = h;
    g_woutl[i] = lo;
}

// ---------------- HMMA GEMM: h16 = [dinv[m] *] (A[M,128] @ W[128,128]) ----------------
template <bool SPLIT, bool SCALE, int MINB>
__global__ __launch_bounds__(256, MINB)
void gemm_hmma(const void* __restrict__ Av, int layer, int M) {
    extern __shared__ __half sm[];
    __half* sAh = sm;
    __half* sAl = sm + 128 * PADH;
    __half* sBh = sm + (SPLIT ? 2 : 1) * 128 * PADH;
    __half* sBl = sBh + 128 * PADH;
    const int tid = threadIdx.x;
    const int wid = tid >> 5;
    const int lane = tid & 31;
    const int row0 = blockIdx.x << 7;

    {
        const float4* wh = (const float4*)g_wpkh + (size_t)layer * 2048;
        const float4* wl = (const float4*)g_wpkl + (size_t)layer * 2048;
#pragma unroll
        for (int i = 0; i < 8; i++) {
            int idx = tid + 256 * i;
            int n = idx >> 4;
            int c8 = (idx & 15) << 3;
            *(float4*)(sBh + n * PADH + c8) = wh[idx];
            *(float4*)(sBl + n * PADH + c8) = wl[idx];
        }
    }
    if (SPLIT) {
        const float* A = (const float*)Av;
#pragma unroll
        for (int i = 0; i < 16; i++) {
            int idx = tid + 256 * i;
            int m = idx >> 5;
            int c4 = (idx & 31) << 2;
            float4 v = make_float4(0.f, 0.f, 0.f, 0.f);
            int gr = row0 + m;
            if (gr < M) v = *(const float4*)(A + (size_t)gr * 128 + c4);
            __half h0 = __float2half_rn(v.x), h1 = __float2half_rn(v.y);
            __half h2 = __float2half_rn(v.z), h3 = __float2half_rn(v.w);
            __half l0 = __float2half_rn(v.x - __half2float(h0));
            __half l1 = __float2half_rn(v.y - __half2float(h1));
            __half l2 = __float2half_rn(v.z - __half2float(h2));
            __half l3 = __float2half_rn(v.w - __half2float(h3));
            __half* ph = sAh + m * PADH + c4;
            __half* pl = sAl + m * PADH + c4;
            *(__half2*)(ph) = __halves2half2(h0, h1);
            *(__half2*)(ph + 2) = __halves2half2(h2, h3);
            *(__half2*)(pl) = __halves2half2(l0, l1);
            *(__half2*)(pl + 2) = __halves2half2(l2, l3);
        }
    } else {
        const uint4* A = (const uint4*)Av;
#pragma unroll
        for (int i = 0; i < 8; i++) {
            int idx = tid + 256 * i;
            int m = idx >> 4;
            int c8 = (idx & 15) << 3;
            uint4 v = make_uint4(0u, 0u, 0u, 0u);
            int gr = row0 + m;
            if (gr < M) v = A[(size_t)gr * 16 + (idx & 15)];
            *(uint4*)(sAh + m * PADH + c8) = v;
        }
    }
    __syncthreads();

    const int wm = wid & 3;
    const int wn = wid >> 2;
    float acc[2][8][4];
#pragma unroll
    for (int mt = 0; mt < 2; mt++)
#pragma unroll
        for (int nt = 0; nt < 8; nt++)
#pragma unroll
            for (int j = 0; j < 4; j++) acc[mt][nt][j] = 0.f;

    const int a_r = lane & 15;
    const int a_c = (lane >> 4) << 3;
    const int b_n = (lane & 7) + ((lane >> 4) << 3);
    const int b_k = ((lane >> 3) & 1) << 3;

#pragma unroll
    for (int k = 0; k < 128; k += 16) {
        uint32_t ah[2][4], al[2][4];
#pragma unroll
        for (int mt = 0; mt < 2; mt++) {
            const int r = (wm * 32 + mt * 16 + a_r) * PADH + k + a_c;
            ldmx4(ah[mt], sAh + r);
            if (SPLIT) ldmx4(al[mt], sAl + r);
        }
        uint32_t bh[8][2], bl[8][2];
#pragma unroll
        for (int p = 0; p < 4; p++) {
            const int off = (wn * 64 + p * 16 + b_n) * PADH + k + b_k;
            uint32_t t[4];
            ldmx4(t, sBh + off);
            bh[2 * p][0] = t[0]; bh[2 * p][1] = t[1];
            bh[2 * p + 1][0] = t[2]; bh[2 * p + 1][1] = t[3];
            ldmx4(t, sBl + off);
            bl[2 * p][0] = t[0]; bl[2 * p][1] = t[1];
            bl[2 * p + 1][0] = t[2]; bl[2 * p + 1][1] = t[3];
        }
#pragma unroll
        for (int mt = 0; mt < 2; mt++)
#pragma unroll
            for (int nt = 0; nt < 8; nt++) {
                mma16816(acc[mt][nt], ah[mt], bh[nt]);
                mma16816(acc[mt][nt], ah[mt], bl[nt]);
                if (SPLIT) mma16816(acc[mt][nt], al[mt], bh[nt]);
            }
    }

    const int r_in = lane >> 2;
    const int cp = lane & 3;
#pragma unroll
    for (int mt = 0; mt < 2; mt++) {
        int gr0 = row0 + wm * 32 + mt * 16 + r_in;
        int gr1 = gr0 + 8;
        float d0 = 1.f, d1 = 1.f;
        if (SCALE) {
            d0 = (gr0 < M) ? g_dinv[gr0] : 0.f;
            d1 = (gr1 < M) ? g_dinv[gr1] : 0.f;
        }
#pragma unroll
        for (int nt = 0; nt < 8; nt++) {
            int cpi = wn * 32 + nt * 4 + cp;
            if (gr0 < M)
                g_h16[(size_t)gr0 * 64 + cpi] =
                    __floats2half2_rn(acc[mt][nt][0] * d0, acc[mt][nt][1] * d0);
            if (gr1 < M)
                g_h16[(size_t)gr1 * 64 + cpi] =
                    __floats2half2_rn(acc[mt][nt][2] * d1, acc[mt][nt][3] * d1);
        }
    }
}

// ---------------- fused aggregate + bias + LayerNorm + ReLU ----------------
// warp per node; 2 edges per iteration: lanes 0-15 gather edge-2i row (uint4 = 8 feats),
// lanes 16-31 gather edge-2i+1. Side partials merged with one shfl_xor(16).
template <bool MULDINV>
__global__ void agg_ln_relu_kernel(const float* __restrict__ cb,
                                   const float* __restrict__ lg,
                                   const float* __restrict__ lb, int N) {
    int n = (blockIdx.x * blockDim.x + threadIdx.x) >> 5;
    int lane = threadIdx.x & 31;
    if (n >= N) return;
    const int h = lane & 15;          // feature chunk: 8*h .. 8*h+7
    const int side = lane >> 4;       // 0: even edges, 1: odd edges
    const int* __restrict__ cs = g_csrc;
    const uint4* __restrict__ hq = (const uint4*)g_h16;   // 16 uint4 per row
    float di = g_dinv[n];

    float a[8];
    {   // self term: side 0 only (side 1 contributes 0; merged later)
        uint4 v = hq[(size_t)n * 16 + h];
        float ws = (side == 0) ? (MULDINV ? di : 1.0f) : 0.0f;
        float2 f0 = __half22float2(*(__half2*)&v.x);
        float2 f1 = __half22float2(*(__half2*)&v.y);
        float2 f2 = __half22float2(*(__half2*)&v.z);
        float2 f3 = __half22float2(*(__half2*)&v.w);
        a[0] = ws * f0.x; a[1] = ws * f0.y; a[2] = ws * f1.x; a[3] = ws * f1.y;
        a[4] = ws * f2.x; a[5] = ws * f2.y; a[6] = ws * f3.x; a[7] = ws * f3.y;
    }
#define ACC8(vv, ww)                                                     \
    {                                                                    \
        float2 f0 = __half22float2(*(__half2*)&(vv).x);                  \
        float2 f1 = __half22float2(*(__half2*)&(vv).y);                  \
        float2 f2 = __half22float2(*(__half2*)&(vv).z);                  \
        float2 f3 = __half22float2(*(__half2*)&(vv).w);                  \
        a[0] = fmaf((ww), f0.x, a[0]); a[1] = fmaf((ww), f0.y, a[1]);    \
        a[2] = fmaf((ww), f1.x, a[2]); a[3] = fmaf((ww), f1.y, a[3]);    \
        a[4] = fmaf((ww), f2.x, a[4]); a[5] = fmaf((ww), f2.y, a[5]);    \
        a[6] = fmaf((ww), f3.x, a[6]); a[7] = fmaf((ww), f3.y, a[7]);    \
    }
    int e = g_start[n];
    int e1 = e + g_deg[n];
    for (; e + 4 <= e1; e += 4) {
        int s0 = cs[e], s1 = cs[e + 1], s2 = cs[e + 2], s3 = cs[e + 3];
        int m0 = side ? s1 : s0;
        int m1 = side ? s3 : s2;
        uint4 r0 = hq[(size_t)m0 * 16 + h];
        uint4 r1 = hq[(size_t)m1 * 16 + h];
        float w0 = MULDINV ? g_dinv[m0] : 1.0f;
        float w1 = MULDINV ? g_dinv[m1] : 1.0f;
        ACC8(r0, w0)
        ACC8(r1, w1)
    }
    if (e + 2 <= e1) {
        int s0 = cs[e], s1 = cs[e + 1];
        int m0 = side ? s1 : s0;
        uint4 r0 = hq[(size_t)m0 * 16 + h];
        float w0 = MULDINV ? g_dinv[m0] : 1.0f;
        ACC8(r0, w0)
        e += 2;
    }
    if (e < e1 && side == 0) {   // odd remainder: side 0 only
        int m0 = cs[e];
        uint4 r0 = hq[(size_t)m0 * 16 + h];
        float w0 = MULDINV ? g_dinv[m0] : 1.0f;
        ACC8(r0, w0)
    }
#undef ACC8
    // merge side partials: both halves then hold full per-feature sums
#pragma unroll
    for (int j = 0; j < 8; j++) a[j] += __shfl_xor_sync(0xffffffffu, a[j], 16);

    int c = h * 8;
    float4 cb0 = *(const float4*)(cb + c);
    float4 cb1 = *(const float4*)(cb + c + 4);
    a[0] = fmaf(di, a[0], cb0.x); a[1] = fmaf(di, a[1], cb0.y);
    a[2] = fmaf(di, a[2], cb0.z); a[3] = fmaf(di, a[3], cb0.w);
    a[4] = fmaf(di, a[4], cb1.x); a[5] = fmaf(di, a[5], cb1.y);
    a[6] = fmaf(di, a[6], cb1.z); a[7] = fmaf(di, a[7], cb1.w);

    // full-warp reductions count every feature twice -> divide by 256
    float s = a[0] + a[1] + a[2] + a[3] + a[4] + a[5] + a[6] + a[7];
#pragma unroll
    for (int o = 16; o > 0; o >>= 1) s += __shfl_xor_sync(0xffffffffu, s, o);
    float mu = s * (1.0f / 256.0f);
    float d[8];
    float v = 0.f;
#pragma unroll
    for (int j = 0; j < 8; j++) { d[j] = a[j] - mu; v = fmaf(d[j], d[j], v); }
#pragma unroll
    for (int o = 16; o > 0; o >>= 1) v += __shfl_xor_sync(0xffffffffu, v, o);
    float inv = rsqrtf(v * (1.0f / 256.0f) + LNEPS);

    float4 lg0 = *(const float4*)(lg + c);
    float4 lg1 = *(const float4*)(lg + c + 4);
    float4 lb0 = *(const float4*)(lb + c);
    float4 lb1 = *(const float4*)(lb + c + 4);
    float o0 = fmaxf(0.f, fmaf(d[0] * inv, lg0.x, lb0.x));
    float o1 = fmaxf(0.f, fmaf(d[1] * inv, lg0.y, lb0.y));
    float o2 = fmaxf(0.f, fmaf(d[2] * inv, lg0.z, lb0.z));
    float o3 = fmaxf(0.f, fmaf(d[3] * inv, lg0.w, lb0.w));
    float o4 = fmaxf(0.f, fmaf(d[4] * inv, lg1.x, lb1.x));
    float o5 = fmaxf(0.f, fmaf(d[5] * inv, lg1.y, lb1.y));
    float o6 = fmaxf(0.f, fmaf(d[6] * inv, lg1.z, lb1.z));
    float o7 = fmaxf(0.f, fmaf(d[7] * inv, lg1.w, lb1.w));
    if (side == 0) {
        uint4 pk;
        __half2 p;
        p = __floats2half2_rn(o0, o1); pk.x = *(unsigned*)&p;
        p = __floats2half2_rn(o2, o3); pk.y = *(unsigned*)&p;
        p = __floats2half2_rn(o4, o5); pk.z = *(unsigned*)&p;
        p = __floats2half2_rn(o6, o7); pk.w = *(unsigned*)&p;
        ((uint4*)g_act16)[(size_t)n * 16 + h] = pk;
    }
}

// ---------------- HMMA output GEMM: out[M,40] = act16 @ (Wh+Wl) + b ----------------
__global__ __launch_bounds__(256, 1)
void out_hmma(const float* __restrict__ bp, float* __restrict__ out, int M) {
    extern __shared__ __half sm2[];
    __half* sX = sm2;
    __half* sBh = sm2 + 128 * PADH;
    __half* sBl = sBh + 48 * PADH;
    const int tid = threadIdx.x;
    const int wid = tid >> 5;
    const int lane = tid & 31;
    const int row0 = blockIdx.x << 7;

    {
        const uint4* wh = (const uint4*)g_wouth;
        const uint4* wl = (const uint4*)g_woutl;
        for (int i = tid; i < 768; i += 256) {
            int n = i >> 4;
            int c8 = (i & 15) << 3;
            *(uint4*)(sBh + n * PADH + c8) = wh[i];
            *(uint4*)(sBl + n * PADH + c8) = wl[i];
        }
    }
    {
        const uint4* X = (const uint4*)g_act16;
#pragma unroll
        for (int i = 0; i < 8; i++) {
            int idx = tid + 256 * i;
            int m = idx >> 4;
            int c8 = (idx & 15) << 3;
            uint4 v = make_uint4(0u, 0u, 0u, 0u);
            int gr = row0 + m;
            if (gr < M) v = X[(size_t)gr * 16 + (idx & 15)];
            *(uint4*)(sX + m * PADH + c8) = v;
        }
    }
    __syncthreads();

    float acc[5][4];
#pragma unroll
    for (int nt = 0; nt < 5; nt++)
#pragma unroll
        for (int j = 0; j < 4; j++) acc[nt][j] = 0.f;

    const int a_r = lane & 15;
    const int a_c = (lane >> 4) << 3;
    const int b_n = (lane & 7) + ((lane >> 4) << 3);
    const int b_k = ((lane >> 3) & 1) << 3;

#pragma unroll
    for (int k = 0; k < 128; k += 16) {
        uint32_t ax[4];
        ldmx4(ax, sX + (wid * 16 + a_r) * PADH + k + a_c);
        uint32_t bh[6][2], bl[6][2];
#pragma unroll
        for (int p = 0; p < 3; p++) {
            const int off = (p * 16 + b_n) * PADH + k + b_k;
            uint32_t t[4];
            ldmx4(t, sBh + off);
            bh[2 * p][0] = t[0]; bh[2 * p][1] = t[1];
            bh[2 * p + 1][0] = t[2]; bh[2 * p + 1][1] = t[3];
            ldmx4(t, sBl + off);
            bl[2 * p][0] = t[0]; bl[2 * p][1] = t[1];
            bl[2 * p + 1][0] = t[2]; bl[2 * p + 1][1] = t[3];
        }
#pragma unroll
        for (int nt = 0; nt < 5; nt++) {
            mma16816(acc[nt], ax, bh[nt]);
            mma16816(acc[nt], ax, bl[nt]);
        }
    }

    const int r_in = lane >> 2;
    const int cp = lane & 3;
    int gr0 = row0 + wid * 16 + r_in;
    int gr1 = gr0 + 8;
#pragma unroll
    for (int nt = 0; nt < 5; nt++) {
        int c0 = nt * 8 + cp * 2;
        float b0 = bp[c0], b1 = bp[c0 + 1];
        if (gr0 < M) {
            float2 o = make_float2(acc[nt][0] + b0, acc[nt][1] + b1);
            *(float2*)(out + (size_t)gr0 * 40 + c0) = o;
        }
        if (gr1 < M) {
            float2 o = make_float2(acc[nt][2] + b0, acc[nt][3] + b1);
            *(float2*)(out + (size_t)gr1 * 40 + c0) = o;
        }
    }
}

// ---------------- launch ----------------
extern "C" void kernel_launch(void* const* d_in, const int* in_sizes, int n_in,
                              void* d_out, int out_size) {
    const float* x      = (const float*)d_in[0];
    const void*  ei     = d_in[1];
    const float* conv_w = (const float*)d_in[2];
    const float* conv_b = (const float*)d_in[3];
    const float* ln_g   = (const float*)d_in[4];
    const float* ln_b   = (const float*)d_in[5];
    const float* wout   = (const float*)d_in[6];
    const float* bout   = (const float*)d_in[7];
    float* out = (float*)d_out;

    const int N = NN;
    const int E = in_sizes[1] / 2;
    const int SMEMSZ4 = 4 * 128 * PADH * 2;
    const int SMEMSZ3 = 3 * 128 * PADH * 2;
    const int OSMEM = (128 * PADH + 2 * 48 * PADH) * 2;

    void* a16;
    cudaGetSymbolAddress(&a16, g_act16);
    cudaFuncSetAttribute((const void*)gemm_hmma<true, false, 1>,
                         cudaFuncAttributeMaxDynamicSharedMemorySize, SMEMSZ4);
    cudaFuncSetAttribute((const void*)gemm_hmma<false, true, 2>,
                         cudaFuncAttributeMaxDynamicSharedMemorySize, SMEMSZ3);
    cudaFuncSetAttribute((const void*)out_hmma,
                         cudaFuncAttributeMaxDynamicSharedMemorySize, OSMEM);

    // fork: weight-prep + layer-0 GEMM overlap the edge-setup chain
    cudaStream_t s2;
    cudaEvent_t evF, evJ;
    cudaStreamCreateWithFlags(&s2, cudaStreamNonBlocking);
    cudaEventCreateWithFlags(&evF, cudaEventDisableTiming);
    cudaEventCreateWithFlags(&evJ, cudaEventDisableTiming);

    cudaEventRecord(evF, 0);
    cudaStreamWaitEvent(s2, evF, 0);
    wprep_kernel<<<192, 256, 0, s2>>>(conv_w);
    wprep_out_kernel<<<24, 256, 0, s2>>>(wout);
    gemm_hmma<true, false, 1><<<(N + 127) / 128, 256, SMEMSZ4, s2>>>((const void*)x, 0, N);
    cudaEventRecord(evJ, s2);

    // edge chain on default stream (R11 configuration)
    detect_zero_kernel<<<100, 512>>>(ei, N);
    convert_count<<<(E / 2 + 255) / 256, 256>>>(ei, E);
    alloc_kernel<<<(N + 1023) / 1024, 1024>>>(N);
    fill_kernel<<<(E / 2 + 255) / 256, 256>>>(ei, E);

    cudaStreamWaitEvent(0, evJ, 0);   // join

    agg_ln_relu_kernel<true><<<(N + 7) / 8, 256>>>(conv_b, ln_g, ln_b, N);
    for (int l = 1; l < 3; l++) {
        gemm_hmma<false, true, 2><<<(N + 127) / 128, 256, SMEMSZ3>>>((const void*)a16, l, N);
        agg_ln_relu_kernel<false><<<(N + 7) / 8, 256>>>(conv_b + (size_t)l * 128,
                                                        ln_g + (size_t)l * 128,
                                                        ln_b + (size_t)l * 128, N);
    }
    out_hmma<<<(N + 127) / 128, 256, OSMEM>>>(bout, out, N);

    cudaStreamCaptureStatus cst = cudaStreamCaptureStatusNone;
    cudaStreamIsCapturing(s2, &cst);
    if (cst == cudaStreamCaptureStatusNone) {
        cudaStreamDestroy(s2);
        cudaEventDestroy(evF);
        cudaEventDestroy(evJ);
    }
}

// round 17
// speedup vs baseline: 1.0354x; 1.0354x over previous
#include <cuda_runtime.h>
#include <cuda_fp16.h>
#include <cstdint>

#define NN 50000
#define EE 800000
#define HIDF 128
#define NCLS 40
#define LNEPS 1e-5f
#define PADH 136   // halves per smem row (272B): ldmatrix conflict-free

typedef unsigned long long ull;

// ---------------- scratch (device globals; no allocation allowed) ----------------
__device__ __half2 g_h16[(size_t)NN * 64];    // post-GEMM features (layer0: unscaled)
__device__ __half2 g_act16[(size_t)NN * 64];  // post-LN activations (fp16)
__device__ float g_dinv[NN];
__device__ int   g_deg[NN];
__device__ int   g_start[NN];
__device__ int   g_rank[EE];
__device__ int   g_csrc[EE];
__device__ int   g_is64;
__device__ int   g_total;
__device__ ull   g_wpkh[12288];              // fp16 hi(W^T): [l][n][k]
__device__ ull   g_wpkl[12288];              // fp16 lo(W^T)
__device__ __half g_wouth[48 * 128];         // fp16 hi(Wout^T), padded n 40->48
__device__ __half g_woutl[48 * 128];         // fp16 lo(Wout^T)

__device__ __forceinline__ uint32_t smem_u32(const void* p) {
    uint32_t a;
    asm("{ .reg .u64 t; cvta.to.shared.u64 t, %1; cvt.u32.u64 %0, t; }" : "=r"(a) : "l"(p));
    return a;
}

// ---------------- HMMA helpers ----------------
__device__ __forceinline__ void mma16816(float* c, const uint32_t* a, const uint32_t* b) {
    asm volatile(
        "mma.sync.aligned.m16n8k16.row.col.f32.f16.f16.f32 "
        "{%0,%1,%2,%3}, {%4,%5,%6,%7}, {%8,%9}, {%0,%1,%2,%3};"
        : "+f"(c[0]), "+f"(c[1]), "+f"(c[2]), "+f"(c[3])
        : "r"(a[0]), "r"(a[1]), "r"(a[2]), "r"(a[3]), "r"(b[0]), "r"(b[1]));
}
__device__ __forceinline__ void ldmx4(uint32_t* r, const __half* p) {
    uint32_t a = smem_u32(p);
    asm volatile("ldmatrix.sync.aligned.m8n8.x4.shared.b16 {%0,%1,%2,%3}, [%4];"
                 : "=r"(r[0]), "=r"(r[1]), "=r"(r[2]), "=r"(r[3]) : "r"(a));
}

// ---------------- setup kernels ----------------
// grid-wide zeroing + 32-lane parallel dtype detect (no serial DRAM chain)
__global__ void detect_zero_kernel(const void* ei, int N) {
    int i = blockIdx.x * blockDim.x + threadIdx.x;
    for (int j = i; j < N; j += gridDim.x * blockDim.x) g_deg[j] = 0;
    if (blockIdx.x == 0 && threadIdx.x < 32) {
        const long long* p = (const long long*)ei;
        int lane = threadIdx.x;
        int bad = 0;
#pragma unroll
        for (int t = 0; t < 2; t++) {
            long long v = p[(lane + 32 * t) * 7];
            if (v < 0 || v >= NN) bad = 1;
        }
        unsigned m = __ballot_sync(0xffffffffu, bad);
        if (lane == 0) {
            g_is64 = (m == 0u);
            g_total = 0;
        }
    }
}

__global__ void convert_count(const void* __restrict__ ei, int E) {
    int e0 = (blockIdx.x * blockDim.x + threadIdx.x) * 2;
    if (e0 >= E) return;
    int d0, d1 = -1;
    if (g_is64) {
        const long long* p = (const long long*)ei;
        d0 = (int)p[E + e0];
        if (e0 + 1 < E) d1 = (int)p[E + e0 + 1];
    } else {
        const int* p = (const int*)ei;
        d0 = p[E + e0];
        if (e0 + 1 < E) d1 = p[E + e0 + 1];
    }
    g_rank[e0] = atomicAdd(&g_deg[d0], 1);
    if (d1 >= 0) g_rank[e0 + 1] = atomicAdd(&g_deg[d1], 1);
}

__global__ void alloc_kernel(int N) {
    __shared__ int warp_sums[32];
    __shared__ int block_base;
    int i = blockIdx.x * blockDim.x + threadIdx.x;
    int lane = threadIdx.x & 31;
    int wid = threadIdx.x >> 5;
    int dg = (i < N) ? g_deg[i] : 0;
    int pre = dg;
#pragma unroll
    for (int o = 1; o < 32; o <<= 1) {
        int v = __shfl_up_sync(0xffffffffu, pre, o);
        if (lane >= o) pre += v;
    }
    int wtot = __shfl_sync(0xffffffffu, pre, 31);
    int wexc = pre - dg;
    if (lane == 31) warp_sums[wid] = wtot;
    __syncthreads();
    if (wid == 0) {
        int v = (lane < (blockDim.x >> 5)) ? warp_sums[lane] : 0;
        int p = v;
#pragma unroll
        for (int o = 1; o < 32; o <<= 1) {
            int t = __shfl_up_sync(0xffffffffu, p, o);
            if (lane >= o) p += t;
        }
        int btot = __shfl_sync(0xffffffffu, p, 31);
        if (lane == 31) block_base = atomicAdd(&g_total, btot);
        p -= v;
        warp_sums[lane] = p;
    }
    __syncthreads();
    if (i < N) {
        g_start[i] = block_base + warp_sums[wid] + wexc;
        g_dinv[i] = rsqrtf((float)dg + 1.0f);
    }
}

__global__ void fill_kernel(const void* __restrict__ ei, int E) {
    int e0 = (blockIdx.x * blockDim.x + threadIdx.x) * 2;
    if (e0 >= E) return;
    int s0, d0, s1 = -1, d1 = -1;
    if (g_is64) {
        const long long* p = (const long long*)ei;
        s0 = (int)p[e0];
        d0 = (int)p[E + e0];
        if (e0 + 1 < E) { s1 = (int)p[e0 + 1]; d1 = (int)p[E + e0 + 1]; }
    } else {
        const int* p = (const int*)ei;
        s0 = p[e0];
        d0 = p[E + e0];
        if (e0 + 1 < E) { s1 = p[e0 + 1]; d1 = p[E + e0 + 1]; }
    }
    int st0 = g_start[d0];
    int rk0 = g_rank[e0];
    int st1 = 0, rk1 = 0;
    if (d1 >= 0) { st1 = g_start[d1]; rk1 = g_rank[e0 + 1]; }
    g_csrc[st0 + rk0] = s0;
    if (d1 >= 0) g_csrc[st1 + rk1] = s1;
}

__global__ void wprep_kernel(const float* __restrict__ cw) {
    int e = blockIdx.x * blockDim.x + threadIdx.x;
    if (e >= 3 * 16384) return;
    int l = e >> 14;
    int r = e & 16383;
    int k = r >> 7;
    int n = r & 127;
    float w = cw[e];
    __half h = __float2half_rn(w);
    __half lo = __float2half_rn(w - __half2float(h));
    size_t off = (size_t)l * 16384 + (size_t)n * 128 + k;
    ((__half*)g_wpkh)[off] = h;
    ((__half*)g_wpkl)[off] = lo;
}

__global__ void wprep_out_kernel(const float* __restrict__ wout) {
    int i = blockIdx.x * blockDim.x + threadIdx.x;
    if (i >= 48 * 128) return;
    int n = i >> 7;
    int k = i & 127;
    float w = (n < NCLS) ? wout[k * NCLS + n] : 0.f;
    __half h = __float2half_rn(w);
    __half lo = __float2half_rn(w - __half2float(h));
    g_wouth[i] = h;
    g_woutl[i] = lo;
}

// ---------------- HMMA GEMM: h16 = [dinv[m] *] (A[M,128] @ W[128,128]) ----------------
// SPLIT=true : A fp32, 3 terms, 4 smem matrices (1 CTA/SM).
// SPLIT=false: A fp16 exact, 2 terms, 3 smem matrices -> 2 CTAs/SM.
template <bool SPLIT, bool SCALE, int MINB>
__global__ __launch_bounds__(256, MINB)
void gemm_hmma(const void* __restrict__ Av, int layer, int M) {
    extern __shared__ __half sm[];
    __half* sAh = sm;
    __half* sAl = sm + 128 * PADH;                       // only used if SPLIT
    __half* sBh = sm + (SPLIT ? 2 : 1) * 128 * PADH;
    __half* sBl = sBh + 128 * PADH;
    const int tid = threadIdx.x;
    const int wid = tid >> 5;
    const int lane = tid & 31;
    const int row0 = blockIdx.x << 7;

    {
        const float4* wh = (const float4*)g_wpkh + (size_t)layer * 2048;
        const float4* wl = (const float4*)g_wpkl + (size_t)layer * 2048;
#pragma unroll
        for (int i = 0; i < 8; i++) {
            int idx = tid + 256 * i;
            int n = idx >> 4;
            int c8 = (idx & 15) << 3;
            *(float4*)(sBh + n * PADH + c8) = wh[idx];
            *(float4*)(sBl + n * PADH + c8) = wl[idx];
        }
    }
    if (SPLIT) {
        const float* A = (const float*)Av;
#pragma unroll
        for (int i = 0; i < 16; i++) {
            int idx = tid + 256 * i;
            int m = idx >> 5;
            int c4 = (idx & 31) << 2;
            float4 v = make_float4(0.f, 0.f, 0.f, 0.f);
            int gr = row0 + m;
            if (gr < M) v = *(const float4*)(A + (size_t)gr * 128 + c4);
            __half h0 = __float2half_rn(v.x), h1 = __float2half_rn(v.y);
            __half h2 = __float2half_rn(v.z), h3 = __float2half_rn(v.w);
            __half l0 = __float2half_rn(v.x - __half2float(h0));
            __half l1 = __float2half_rn(v.y - __half2float(h1));
            __half l2 = __float2half_rn(v.z - __half2float(h2));
            __half l3 = __float2half_rn(v.w - __half2float(h3));
            __half* ph = sAh + m * PADH + c4;
            __half* pl = sAl + m * PADH + c4;
            *(__half2*)(ph) = __halves2half2(h0, h1);
            *(__half2*)(ph + 2) = __halves2half2(h2, h3);
            *(__half2*)(pl) = __halves2half2(l0, l1);
            *(__half2*)(pl + 2) = __halves2half2(l2, l3);
        }
    } else {
        const uint4* A = (const uint4*)Av;
#pragma unroll
        for (int i = 0; i < 8; i++) {
            int idx = tid + 256 * i;
            int m = idx >> 4;
            int c8 = (idx & 15) << 3;
            uint4 v = make_uint4(0u, 0u, 0u, 0u);
            int gr = row0 + m;
            if (gr < M) v = A[(size_t)gr * 16 + (idx & 15)];
            *(uint4*)(sAh + m * PADH + c8) = v;
        }
    }
    __syncthreads();

    const int wm = wid & 3;
    const int wn = wid >> 2;
    float acc[2][8][4];
#pragma unroll
    for (int mt = 0; mt < 2; mt++)
#pragma unroll
        for (int nt = 0; nt < 8; nt++)
#pragma unroll
            for (int j = 0; j < 4; j++) acc[mt][nt][j] = 0.f;

    const int a_r = lane & 15;
    const int a_c = (lane >> 4) << 3;
    const int b_n = (lane & 7) + ((lane >> 4) << 3);
    const int b_k = ((lane >> 3) & 1) << 3;

#pragma unroll
    for (int k = 0; k < 128; k += 16) {
        uint32_t ah[2][4], al[2][4];
#pragma unroll
        for (int mt = 0; mt < 2; mt++) {
            const int r = (wm * 32 + mt * 16 + a_r) * PADH + k + a_c;
            ldmx4(ah[mt], sAh + r);
            if (SPLIT) ldmx4(al[mt], sAl + r);
        }
        uint32_t bh[8][2], bl[8][2];
#pragma unroll
        for (int p = 0; p < 4; p++) {
            const int off = (wn * 64 + p * 16 + b_n) * PADH + k + b_k;
            uint32_t t[4];
            ldmx4(t, sBh + off);
            bh[2 * p][0] = t[0]; bh[2 * p][1] = t[1];
            bh[2 * p + 1][0] = t[2]; bh[2 * p + 1][1] = t[3];
            ldmx4(t, sBl + off);
            bl[2 * p][0] = t[0]; bl[2 * p][1] = t[1];
            bl[2 * p + 1][0] = t[2]; bl[2 * p + 1][1] = t[3];
        }
#pragma unroll
        for (int mt = 0; mt < 2; mt++)
#pragma unroll
            for (int nt = 0; nt < 8; nt++) {
                mma16816(acc[mt][nt], ah[mt], bh[nt]);
                mma16816(acc[mt][nt], ah[mt], bl[nt]);
                if (SPLIT) mma16816(acc[mt][nt], al[mt], bh[nt]);
            }
    }

    const int r_in = lane >> 2;
    const int cp = lane & 3;
#pragma unroll
    for (int mt = 0; mt < 2; mt++) {
        int gr0 = row0 + wm * 32 + mt * 16 + r_in;
        int gr1 = gr0 + 8;
        float d0 = 1.f, d1 = 1.f;
        if (SCALE) {
            d0 = (gr0 < M) ? g_dinv[gr0] : 0.f;
            d1 = (gr1 < M) ? g_dinv[gr1] : 0.f;
        }
#pragma unroll
        for (int nt = 0; nt < 8; nt++) {
            int cpi = wn * 32 + nt * 4 + cp;
            if (gr0 < M)
                g_h16[(size_t)gr0 * 64 + cpi] =
                    __floats2half2_rn(acc[mt][nt][0] * d0, acc[mt][nt][1] * d0);
            if (gr1 < M)
                g_h16[(size_t)gr1 * 64 + cpi] =
                    __floats2half2_rn(acc[mt][nt][2] * d1, acc[mt][nt][3] * d1);
        }
    }
}

// ---------------- fused aggregate + bias + LayerNorm + ReLU (warp per node) ----------------
template <bool MULDINV>
__global__ void agg_ln_relu_kernel(const float* __restrict__ cb,
                                   const float* __restrict__ lg,
                                   const float* __restrict__ lb, int N) {
    int n = (blockIdx.x * blockDim.x + threadIdx.x) >> 5;
    int lane = threadIdx.x & 31;
    if (n >= N) return;
    const int* __restrict__ cs = g_csrc;
    const ull* __restrict__ hrow = (const ull*)g_h16 + lane;
    float di = g_dinv[n];

    float a0, a1, a2, a3;
    {
        ull v = hrow[(size_t)n * 32];
        float2 f0 = __half22float2(*(__half2*)&v);
        float2 f1 = __half22float2(*((__half2*)&v + 1));
        float ws = MULDINV ? di : 1.0f;
        a0 = ws * f0.x; a1 = ws * f0.y; a2 = ws * f1.x; a3 = ws * f1.y;
    }
#define ACCW(v, w)                                               \
    {                                                            \
        float2 f0 = __half22float2(*(__half2*)&(v));             \
        float2 f1 = __half22float2(*((__half2*)&(v) + 1));       \
        a0 = fmaf((w), f0.x, a0); a1 = fmaf((w), f0.y, a1);      \
        a2 = fmaf((w), f1.x, a2); a3 = fmaf((w), f1.y, a3);      \
    }
    int e = g_start[n];
    int e1 = e + g_deg[n];
    for (; e + 8 <= e1; e += 8) {
        int s0 = cs[e], s1 = cs[e + 1], s2 = cs[e + 2], s3 = cs[e + 3];
        int s4 = cs[e + 4], s5 = cs[e + 5], s6 = cs[e + 6], s7 = cs[e + 7];
        ull v0 = hrow[(size_t)s0 * 32];
        ull v1 = hrow[(size_t)s1 * 32];
        ull v2 = hrow[(size_t)s2 * 32];
        ull v3 = hrow[(size_t)s3 * 32];
        ull v4 = hrow[(size_t)s4 * 32];
        ull v5 = hrow[(size_t)s5 * 32];
        ull v6 = hrow[(size_t)s6 * 32];
        ull v7 = hrow[(size_t)s7 * 32];
        float w0 = MULDINV ? g_dinv[s0] : 1.0f;
        float w1 = MULDINV ? g_dinv[s1] : 1.0f;
        float w2 = MULDINV ? g_dinv[s2] : 1.0f;
        float w3 = MULDINV ? g_dinv[s3] : 1.0f;
        float w4 = MULDINV ? g_dinv[s4] : 1.0f;
        float w5 = MULDINV ? g_dinv[s5] : 1.0f;
        float w6 = MULDINV ? g_dinv[s6] : 1.0f;
        float w7 = MULDINV ? g_dinv[s7] : 1.0f;
        ACCW(v0, w0) ACCW(v1, w1) ACCW(v2, w2) ACCW(v3, w3)
        ACCW(v4, w4) ACCW(v5, w5) ACCW(v6, w6) ACCW(v7, w7)
    }
    for (; e < e1; e++) {
        int s0 = cs[e];
        ull v = hrow[(size_t)s0 * 32];
        float w = MULDINV ? g_dinv[s0] : 1.0f;
        ACCW(v, w)
    }
#undef ACCW
    int c = lane * 4;
    a0 = fmaf(di, a0, cb[c]);
    a1 = fmaf(di, a1, cb[c + 1]);
    a2 = fmaf(di, a2, cb[c + 2]);
    a3 = fmaf(di, a3, cb[c + 3]);
    float s = a0 + a1 + a2 + a3;
#pragma unroll
    for (int o = 16; o > 0; o >>= 1) s += __shfl_xor_sync(0xffffffffu, s, o);
    float mu = s * (1.0f / 128.0f);
    float d0 = a0 - mu, d1 = a1 - mu, d2 = a2 - mu, d3 = a3 - mu;
    float v = d0 * d0 + d1 * d1 + d2 * d2 + d3 * d3;
#pragma unroll
    for (int o = 16; o > 0; o >>= 1) v += __shfl_xor_sync(0xffffffffu, v, o);
    float inv = rsqrtf(v * (1.0f / 128.0f) + LNEPS);
    float o0 = fmaxf(0.f, fmaf(d0 * inv, lg[c + 0], lb[c + 0]));
    float o1 = fmaxf(0.f, fmaf(d1 * inv, lg[c + 1], lb[c + 1]));
    float o2 = fmaxf(0.f, fmaf(d2 * inv, lg[c + 2], lb[c + 2]));
    float o3 = fmaxf(0.f, fmaf(d3 * inv, lg[c + 3], lb[c + 3]));
    __half2 p0 = __floats2half2_rn(o0, o1);
    __half2 p1 = __floats2half2_rn(o2, o3);
    ull pk = (ull)*(unsigned*)&p0 | ((ull)*(unsigned*)&p1 << 32);
    ((ull*)g_act16)[(size_t)n * 32 + lane] = pk;
}

// ---------------- HMMA output GEMM: out[M,40] = act16 @ (Wh+Wl) + b ----------------
__global__ __launch_bounds__(256, 1)
void out_hmma(const float* __restrict__ bp, float* __restrict__ out, int M) {
    extern __shared__ __half sm2[];
    __half* sX = sm2;
    __half* sBh = sm2 + 128 * PADH;
    __half* sBl = sBh + 48 * PADH;
    const int tid = threadIdx.x;
    const int wid = tid >> 5;
    const int lane = tid & 31;
    const int row0 = blockIdx.x << 7;

    {
        const uint4* wh = (const uint4*)g_wouth;
        const uint4* wl = (const uint4*)g_woutl;
        for (int i = tid; i < 768; i += 256) {
            int n = i >> 4;
            int c8 = (i & 15) << 3;
            *(uint4*)(sBh + n * PADH + c8) = wh[i];
            *(uint4*)(sBl + n * PADH + c8) = wl[i];
        }
    }
    {
        const uint4* X = (const uint4*)g_act16;
#pragma unroll
        for (int i = 0; i < 8; i++) {
            int idx = tid + 256 * i;
            int m = idx >> 4;
            int c8 = (idx & 15) << 3;
            uint4 v = make_uint4(0u, 0u, 0u, 0u);
            int gr = row0 + m;
            if (gr < M) v = X[(size_t)gr * 16 + (idx & 15)];
            *(uint4*)(sX + m * PADH + c8) = v;
        }
    }
    __syncthreads();

    float acc[5][4];
#pragma unroll
    for (int nt = 0; nt < 5; nt++)
#pragma unroll
        for (int j = 0; j < 4; j++) acc[nt][j] = 0.f;

    const int a_r = lane & 15;
    const int a_c = (lane >> 4) << 3;
    const int b_n = (lane & 7) + ((lane >> 4) << 3);
    const int b_k = ((lane >> 3) & 1) << 3;

#pragma unroll
    for (int k = 0; k < 128; k += 16) {
        uint32_t ax[4];
        ldmx4(ax, sX + (wid * 16 + a_r) * PADH + k + a_c);
        uint32_t bh[6][2], bl[6][2];
#pragma unroll
        for (int p = 0; p < 3; p++) {
            const int off = (p * 16 + b_n) * PADH + k + b_k;
            uint32_t t[4];
            ldmx4(t, sBh + off);
            bh[2 * p][0] = t[0]; bh[2 * p][1] = t[1];
            bh[2 * p + 1][0] = t[2]; bh[2 * p + 1][1] = t[3];
            ldmx4(t, sBl + off);
            bl[2 * p][0] = t[0]; bl[2 * p][1] = t[1];
            bl[2 * p + 1][0] = t[2]; bl[2 * p + 1][1] = t[3];
        }
#pragma unroll
        for (int nt = 0; nt < 5; nt++) {
            mma16816(acc[nt], ax, bh[nt]);
            mma16816(acc[nt], ax, bl[nt]);
        }
    }

    const int r_in = lane >> 2;
    const int cp = lane & 3;
    int gr0 = row0 + wid * 16 + r_in;
    int gr1 = gr0 + 8;
#pragma unroll
    for (int nt = 0; nt < 5; nt++) {
        int c0 = nt * 8 + cp * 2;
        float b0 = bp[c0], b1 = bp[c0 + 1];
        if (gr0 < M) {
            float2 o = make_float2(acc[nt][0] + b0, acc[nt][1] + b1);
            *(float2*)(out + (size_t)gr0 * 40 + c0) = o;
        }
        if (gr1 < M) {
            float2 o = make_float2(acc[nt][2] + b0, acc[nt][3] + b1);
            *(float2*)(out + (size_t)gr1 * 40 + c0) = o;
        }
    }
}

// ---------------- launch ----------------
extern "C" void kernel_launch(void* const* d_in, const int* in_sizes, int n_in,
                              void* d_out, int out_size) {
    const float* x      = (const float*)d_in[0];
    const void*  ei     = d_in[1];
    const float* conv_w = (const float*)d_in[2];
    const float* conv_b = (const float*)d_in[3];
    const float* ln_g   = (const float*)d_in[4];
    const float* ln_b   = (const float*)d_in[5];
    const float* wout   = (const float*)d_in[6];
    const float* bout   = (const float*)d_in[7];
    float* out = (float*)d_out;

    const int N = NN;
    const int E = in_sizes[1] / 2;
    const int SMEMSZ4 = 4 * 128 * PADH * 2;          // 139264 B (split, 1 CTA/SM)
    const int SMEMSZ3 = 3 * 128 * PADH * 2;          // 104448 B (2-term, 2 CTA/SM)
    const int OSMEM = (128 * PADH + 2 * 48 * PADH) * 2;

    void* a16;
    cudaGetSymbolAddress(&a16, g_act16);
    cudaFuncSetAttribute((const void*)gemm_hmma<true, false, 1>,
                         cudaFuncAttributeMaxDynamicSharedMemorySize, SMEMSZ4);
    cudaFuncSetAttribute((const void*)gemm_hmma<false, true, 2>,
                         cudaFuncAttributeMaxDynamicSharedMemorySize, SMEMSZ3);
    cudaFuncSetAttribute((const void*)out_hmma,
                         cudaFuncAttributeMaxDynamicSharedMemorySize, OSMEM);

    // fork: weight-prep + layer-0 GEMM overlap the edge-setup chain
    cudaStream_t s2;
    cudaEvent_t evF, evJ;
    cudaStreamCreateWithFlags(&s2, cudaStreamNonBlocking);
    cudaEventCreateWithFlags(&evF, cudaEventDisableTiming);
    cudaEventCreateWithFlags(&evJ, cudaEventDisableTiming);

    cudaEventRecord(evF, 0);
    cudaStreamWaitEvent(s2, evF, 0);
    wprep_kernel<<<192, 256, 0, s2>>>(conv_w);
    wprep_out_kernel<<<24, 256, 0, s2>>>(wout);
    gemm_hmma<true, false, 1><<<(N + 127) / 128, 256, SMEMSZ4, s2>>>((const void*)x, 0, N);
    cudaEventRecord(evJ, s2);

    detect_zero_kernel<<<100, 512>>>(ei, N);
    convert_count<<<(E / 2 + 255) / 256, 256>>>(ei, E);
    alloc_kernel<<<(N + 1023) / 1024, 1024>>>(N);
    fill_kernel<<<(E / 2 + 255) / 256, 256>>>(ei, E);

    cudaStreamWaitEvent(0, evJ, 0);   // join

    agg_ln_relu_kernel<true><<<(N + 7) / 8, 256>>>(conv_b, ln_g, ln_b, N);
    for (int l = 1; l < 3; l++) {
        gemm_hmma<false, true, 2><<<(N + 127) / 128, 256, SMEMSZ3>>>((const void*)a16, l, N);
        agg_ln_relu_kernel<false><<<(N + 7) / 8, 256>>>(conv_b + (size_t)l * 128,
                                                        ln_g + (size_t)l * 128,
                                                        ln_b + (size_t)l * 128, N);
    }
    out_hmma<<<(N + 127) / 128, 256, OSMEM>>>(bout, out, N);

    cudaStreamCaptureStatus cst = cudaStreamCaptureStatusNone;
    cudaStreamIsCapturing(s2, &cst);
    if (cst == cudaStreamCaptureStatusNone) {
        cudaStreamDestroy(s2);
        cudaEventDestroy(evF);
        cudaEventDestroy(evJ);
    }
}